// round 8
// baseline (speedup 1.0000x reference)
#include <cuda_runtime.h>
#include <cuda_bf16.h>
#include <math.h>

// ---------------------------------------------------------------------------
// SRNN ALIF — bit-exact-vs-XLA-CPU fp32, optimized (round 8).
// GEMMs: serial ascending-k fp32 FMA chain per output, 2 rows packed per
//        fma.rn.f32x2. Operands come out of SMEM pre-packed: A pairs via
//        direct LDS.64, W pre-duplicated (w,w) at tile load. Zero movs in loop.
// Elementwise: explicit non-contracted fp32 ops. exp: XLA Cephes polynomial.
// ---------------------------------------------------------------------------

#define T_STEPS 100
#define NBATCH  64
#define HID     512
#define INSZ    1024

__device__ float d_xp  [2 * T_STEPS * NBATCH * INSZ];   // pooled [c][t][n][1024]
__device__ float d_in12[2 * T_STEPS * NBATCH * HID];    // ff proj [c][t][n][512]
__device__ float d_s12 [T_STEPS * NBATCH * INSZ];       // spikes s1||s2 [t][n][1024]
__device__ float d_ff3 [T_STEPS * NBATCH * HID];        // concat@W1 (+b1) [t][n][512]
__device__ float d_wt  [HID * HID];                     // w_h2h3 transposed [j][i]

// ---------------------------------------------------------------------------
// XLA:CPU exp — Cephes/Eigen pexp<float> with FMA, exact op order.
// ---------------------------------------------------------------------------
__device__ __forceinline__ float xla_expf(float x) {
    const float exp_hi = 88.723164f, exp_lo = -88.723164f;
    x = fminf(fmaxf(x, exp_lo), exp_hi);
    float m = floorf(__fmaf_rn(x, 1.44269504088896341f, 0.5f));
    float r = __fmaf_rn(m, -0.693359375f, x);
    r = __fmaf_rn(m, 2.12194440e-4f, r);
    float r2 = __fmul_rn(r, r);
    float y = 1.9875691500e-4f;
    y = __fmaf_rn(y, r, 1.3981999507e-3f);
    y = __fmaf_rn(y, r, 8.3334519073e-3f);
    y = __fmaf_rn(y, r, 4.1665795894e-2f);
    y = __fmaf_rn(y, r, 1.6666665459e-1f);
    y = __fmaf_rn(y, r, 5.0000001201e-1f);
    y = __fmaf_rn(y, r2, r);
    y = __fadd_rn(y, 1.0f);
    return ldexpf(y, (int)m);
}

__device__ __forceinline__ float alpha_of(float tau) {
    return xla_expf(__fdiv_rn(-1.0f, tau));
}

__device__ __forceinline__ void upk2(unsigned long long v, float& lo, float& hi) {
    asm("mov.b64 {%0, %1}, %2;" : "=f"(lo), "=f"(hi) : "l"(v));
}
__device__ __forceinline__ unsigned long long pk2(float lo, float hi) {
    unsigned long long r;
    asm("mov.b64 %0, {%1, %2};" : "=l"(r) : "f"(lo), "f"(hi));
    return r;
}
__device__ __forceinline__ unsigned long long fma2(unsigned long long a,
                                                   unsigned long long b,
                                                   unsigned long long c) {
    unsigned long long d;
    asm("fma.rn.f32x2 %0, %1, %2, %3;" : "=l"(d) : "l"(a), "l"(b), "l"(c));
    return d;
}

// ---------------------------------------------------------------------------
// 1) maxpool 4x4 stride 4 (exact): x[n][t][c][128][128] -> xp[c][t][n][1024]
// ---------------------------------------------------------------------------
__global__ void pool_kernel(const float* __restrict__ x) {
    int tid = blockIdx.x * blockDim.x + threadIdx.x;
    int i    = tid & 1023;
    int n    = (tid >> 10) & 63;
    int rest = tid >> 16;          // c*100 + t
    int t    = rest % 100;
    int c    = rest / 100;
    int ph = i >> 5, pw = i & 31;
    const float* base = x + (((size_t)(n * 100 + t) * 2 + c) << 14) + ph * 512 + pw * 4;
    float mx = -3.4e38f;
#pragma unroll
    for (int r = 0; r < 4; r++) {
        float4 v = *(const float4*)(base + r * 128);
        mx = fmaxf(mx, fmaxf(fmaxf(v.x, v.y), fmaxf(v.z, v.w)));
    }
    d_xp[tid] = mx;
}

// ---------------------------------------------------------------------------
// 2) fp32 GEMM (NT), f32x2-packed with pre-packed SMEM operands:
//    C[6400][512] = A[6400][1024] * W[512][1024]^T + bias
//    BM=128, BN=64, BK=32. 256 thr, 8 rows (4 ull pairs) x 4 cols per thread.
// ---------------------------------------------------------------------------
#define BM 128
#define BN 64
#define BK 32
__global__ __launch_bounds__(256)
void gemm_nt(const float* __restrict__ A, const float* __restrict__ W,
             const float* __restrict__ bias_a, float* __restrict__ C) {
    __shared__ float              As [BK][BM];   // 16 KB, [k][m]
    __shared__ unsigned long long Ws2[BK][BN];   // 16 KB, [k][n] = (w,w)
    int tid = threadIdx.x;
    int rowBase = blockIdx.y * BM;
    int colBase = blockIdx.x * BN;
    int tx = tid & 15;    // cols tx*4..+3
    int ty = tid >> 4;    // rows ty*8..+7 (4 packed pairs)
    unsigned long long acc2[4][4];
#pragma unroll
    for (int rp = 0; rp < 4; rp++)
#pragma unroll
        for (int c = 0; c < 4; c++) acc2[rp][c] = 0ULL;

    for (int k0 = 0; k0 < 1024; k0 += BK) {
        __syncthreads();
#pragma unroll
        for (int u = 0; u < 4; u++) {             // A: 1024 float4 slots
            int s = tid + u * 256;
            int m = s >> 3, kq = s & 7;
            float4 v = *(const float4*)&A[(size_t)(rowBase + m) * 1024 + k0 + kq * 4];
            As[kq * 4 + 0][m] = v.x; As[kq * 4 + 1][m] = v.y;
            As[kq * 4 + 2][m] = v.z; As[kq * 4 + 3][m] = v.w;
        }
#pragma unroll
        for (int u = 0; u < 2; u++) {             // W: 512 float4 slots, duplicated
            int s = tid + u * 256;
            int nn = s >> 3, kq = s & 7;
            float4 v = *(const float4*)&W[(size_t)(colBase + nn) * 1024 + k0 + kq * 4];
            Ws2[kq * 4 + 0][nn] = pk2(v.x, v.x);
            Ws2[kq * 4 + 1][nn] = pk2(v.y, v.y);
            Ws2[kq * 4 + 2][nn] = pk2(v.z, v.z);
            Ws2[kq * 4 + 3][nn] = pk2(v.w, v.w);
        }
        __syncthreads();
        // strict ascending k; each output keeps its own serial fp32 chain
#pragma unroll
        for (int k = 0; k < BK; k++) {
            unsigned long long apk[4], wpk[4];
#pragma unroll
            for (int rp = 0; rp < 4; rp++)
                apk[rp] = *(const unsigned long long*)&As[k][ty * 8 + rp * 2];  // LDS.64
#pragma unroll
            for (int c = 0; c < 4; c++)
                wpk[c] = Ws2[k][tx * 4 + c];                                    // LDS.64
#pragma unroll
            for (int rp = 0; rp < 4; rp++)
#pragma unroll
                for (int c = 0; c < 4; c++)
                    acc2[rp][c] = fma2(apk[rp], wpk[c], acc2[rp][c]);
        }
    }
    float badd[4];
#pragma unroll
    for (int c = 0; c < 4; c++)
        badd[c] = bias_a ? bias_a[colBase + tx * 4 + c] : 0.f;   // zeros in practice
#pragma unroll
    for (int rp = 0; rp < 4; rp++) {
        size_t off0 = (size_t)(rowBase + ty * 8 + rp * 2 + 0) * 512 + colBase + tx * 4;
        size_t off1 = (size_t)(rowBase + ty * 8 + rp * 2 + 1) * 512 + colBase + tx * 4;
#pragma unroll
        for (int c = 0; c < 4; c++) {
            float lo, hi;
            upk2(acc2[rp][c], lo, hi);
            C[off0 + c] = __fadd_rn(lo, badd[c]);
            C[off1 + c] = __fadd_rn(hi, badd[c]);
        }
    }
}

// ---------------------------------------------------------------------------
// ALIF update: XLA HLO op-for-op — every op individually rounded, no FMA.
// ---------------------------------------------------------------------------
__device__ __forceinline__ void alif(float inp, float& m, float& s, float& bb,
                                     float alpha, float omAlpha, float ro, float omRo) {
    bb = __fadd_rn(__fmul_rn(ro, bb), __fmul_rn(omRo, s));
    float B = __fadd_rn(0.1f, __fmul_rn(1.8f, bb));
    float t1 = __fadd_rn(__fmul_rn(m, alpha), __fmul_rn(omAlpha, inp));
    m = __fsub_rn(t1, __fmul_rn(B, s));
    s = (__fsub_rn(m, B) > 0.f) ? 1.f : 0.f;
}

// ---------------------------------------------------------------------------
// 3) Layers 1 & 2 scans — parallel per neuron, 4-deep load pipeline (MLP=4)
// ---------------------------------------------------------------------------
__global__ void scan12_kernel(const float* __restrict__ tau_adp1, const float* __restrict__ tau_adp2,
                              const float* __restrict__ tau_m1,  const float* __restrict__ tau_m2) {
    int tid = blockIdx.x * blockDim.x + threadIdx.x;   // 65536
    int h = tid & 511;
    int n = (tid >> 9) & 63;
    int layer = tid >> 15;
    float alpha = alpha_of(layer ? tau_m2[h]   : tau_m1[h]);
    float ro    = alpha_of(layer ? tau_adp2[h] : tau_adp1[h]);
    float omA = __fsub_rn(1.0f, alpha);
    float omR = __fsub_rn(1.0f, ro);
    float m = 0.f, bb = 0.1f, s = 0.f;
    const float* inbase = d_in12 + (size_t)layer * T_STEPS * NBATCH * HID + (size_t)n * HID + h;
    float* sbase = d_s12 + (size_t)n * INSZ + layer * HID + h;

    float buf[4];
#pragma unroll
    for (int j = 0; j < 4; j++) buf[j] = inbase[(size_t)j * NBATCH * HID];
    for (int t = 0; t < T_STEPS; t++) {
        float inp = buf[t & 3];
        if (t + 4 < T_STEPS) buf[t & 3] = inbase[(size_t)(t + 4) * NBATCH * HID];
        alif(inp, m, s, bb, alpha, omA, ro, omR);
        sbase[(size_t)t * NBATCH * INSZ] = s;
    }
}

// ---------------------------------------------------------------------------
// 4) transpose w_h2h3 [512][512] -> wt[j][i]  (pure copy, exact)
// ---------------------------------------------------------------------------
__global__ void transpose512(const float* __restrict__ w) {
    __shared__ float tile[32][33];
    int bx = blockIdx.x * 32, by = blockIdx.y * 32;
#pragma unroll
    for (int r = 0; r < 4; r++)
        tile[threadIdx.y + 8 * r][threadIdx.x] = w[(size_t)(by + threadIdx.y + 8 * r) * 512 + bx + threadIdx.x];
    __syncthreads();
#pragma unroll
    for (int r = 0; r < 4; r++)
        d_wt[(size_t)(bx + threadIdx.y + 8 * r) * 512 + by + threadIdx.x] =
            tile[threadIdx.x][threadIdx.y + 8 * r];
}

// ---------------------------------------------------------------------------
// 5) Layer-3 sequential scan. One CTA/batch, one thread/neuron.
//    Parity-double-buffered active list -> 2 barriers/step.
//    recur = single serial ascending-j fp32 add chain (bit-exact vs dense).
// ---------------------------------------------------------------------------
__global__ __launch_bounds__(512)
void layer3_kernel(const float* __restrict__ w_h2o3, const float* __restrict__ b_h2o3,
                   const float* __restrict__ b_h2h3,
                   const float* __restrict__ tau_adp, const float* __restrict__ tau_m,
                   float* __restrict__ out) {
    int n = blockIdx.x;      // batch
    int i = threadIdx.x;     // neuron
    __shared__ int   list[2][512];
    __shared__ int   warpcnt[2][16];
    __shared__ float s3sm[512];

    float alpha = alpha_of(tau_m[i]);
    float ro    = alpha_of(tau_adp[i]);
    float omA = __fsub_rn(1.0f, alpha);
    float omR = __fsub_rn(1.0f, ro);
    float b2  = b_h2h3[i];   // zero in practice
    float m = 0.f, bb = 0.1f, s = 0.f;
    int wid = i >> 5, lane = i & 31;
    unsigned lanemask = (1u << lane) - 1u;

    for (int t = 0; t < T_STEPS; t++) {
        int p = t & 1;
        unsigned mask = __ballot_sync(0xffffffffu, s != 0.f);
        if (lane == 0) warpcnt[p][wid] = __popc(mask);
        __syncthreads();
        int off = 0, total = 0;
#pragma unroll
        for (int w = 0; w < 16; w++) { int c = warpcnt[p][w]; total += c; if (w < wid) off += c; }
        if (s != 0.f) list[p][off + __popc(mask & lanemask)] = i;   // ascending j
        __syncthreads();

        float recur = 0.f;
#pragma unroll 4
        for (int k = 0; k < total; k++)
            recur = __fadd_rn(recur, d_wt[(size_t)list[p][k] * 512 + i]);

        float ffv = d_ff3[((size_t)t * NBATCH + n) * HID + i];   // concat@W1 + b1
        float inp = __fadd_rn(__fadd_rn(ffv, recur), b2);        // ((..)+recur)+b2
        alif(inp, m, s, bb, alpha, omA, ro, omR);
    }
    s3sm[i] = s;
    __syncthreads();
    if (i < 11) {
        float acc = 0.f;
        for (int j = 0; j < 512; j++)
            acc = __fmaf_rn(s3sm[j], w_h2o3[(size_t)i * 512 + j], acc);
        out[n * 11 + i] = __fadd_rn(acc, b_h2o3[i]);
    }
}

// ---------------------------------------------------------------------------
extern "C" void kernel_launch(void* const* d_in, const int* in_sizes, int n_in,
                              void* d_out, int out_size) {
    const float* x          = (const float*)d_in[0];
    const float* w_i2h1     = (const float*)d_in[1];
    const float* b_i2h1     = (const float*)d_in[2];
    const float* w_i2h2     = (const float*)d_in[3];
    const float* b_i2h2     = (const float*)d_in[4];
    const float* w_i2h3     = (const float*)d_in[5];
    const float* b_i2h3     = (const float*)d_in[6];
    const float* w_h2h3     = (const float*)d_in[7];
    const float* b_h2h3     = (const float*)d_in[8];
    const float* w_h2o3     = (const float*)d_in[9];
    const float* b_h2o3     = (const float*)d_in[10];
    const float* tau_adp_h1 = (const float*)d_in[11];
    const float* tau_adp_h2 = (const float*)d_in[12];
    const float* tau_adp_h3 = (const float*)d_in[13];
    const float* tau_m_h1   = (const float*)d_in[14];
    const float* tau_m_h2   = (const float*)d_in[15];
    const float* tau_m_h3   = (const float*)d_in[16];
    float* out = (float*)d_out;

    float *xp, *in12, *s12, *ff3;
    cudaGetSymbolAddress((void**)&xp,   d_xp);
    cudaGetSymbolAddress((void**)&in12, d_in12);
    cudaGetSymbolAddress((void**)&s12,  d_s12);
    cudaGetSymbolAddress((void**)&ff3,  d_ff3);

    pool_kernel<<<51200, 256>>>(x);

    dim3 ggrid(512 / BN, 6400 / BM);
    gemm_nt<<<ggrid, 256>>>(xp,                                   w_i2h1, b_i2h1, in12);
    gemm_nt<<<ggrid, 256>>>(xp + (size_t)T_STEPS * NBATCH * INSZ, w_i2h2, b_i2h2,
                            in12 + (size_t)T_STEPS * NBATCH * HID);

    scan12_kernel<<<256, 256>>>(tau_adp_h1, tau_adp_h2, tau_m_h1, tau_m_h2);

    transpose512<<<dim3(16, 16), dim3(32, 8)>>>(w_h2h3);

    gemm_nt<<<ggrid, 256>>>(s12, w_i2h3, b_i2h3, ff3);

    layer3_kernel<<<NBATCH, 512>>>(w_h2o3, b_h2o3, b_h2h3, tau_adp_h3, tau_m_h3, out);
}

// round 9
// speedup vs baseline: 1.1992x; 1.1992x over previous
#include <cuda_runtime.h>
#include <cuda_bf16.h>
#include <math.h>

// ---------------------------------------------------------------------------
// SRNN ALIF — bit-exact-vs-XLA-CPU fp32 (round 9).
// GEMM math identical to round 6 (scalar FFMA, serial ascending-k chain per
// output). New: persistent CTAs + atomic tile stealing, GEMM1+2 merged.
// ---------------------------------------------------------------------------

#define T_STEPS 100
#define NBATCH  64
#define HID     512
#define INSZ    1024

__device__ float d_xp  [2 * T_STEPS * NBATCH * INSZ];   // pooled [c][t][n][1024]
__device__ float d_in12[2 * T_STEPS * NBATCH * HID];    // ff proj [c][t][n][512]
__device__ float d_s12 [T_STEPS * NBATCH * INSZ];       // spikes s1||s2 [t][n][1024]
__device__ float d_ff3 [T_STEPS * NBATCH * HID];        // concat@W1 (+b1) [t][n][512]
__device__ float d_wt  [HID * HID];                     // w_h2h3 transposed [j][i]
__device__ int   d_ctr12;                               // tile counter, GEMM1+2
__device__ int   d_ctr3;                                // tile counter, GEMM3

// ---------------------------------------------------------------------------
// XLA:CPU exp — Cephes/Eigen pexp<float> with FMA, exact op order.
// ---------------------------------------------------------------------------
__device__ __forceinline__ float xla_expf(float x) {
    const float exp_hi = 88.723164f, exp_lo = -88.723164f;
    x = fminf(fmaxf(x, exp_lo), exp_hi);
    float m = floorf(__fmaf_rn(x, 1.44269504088896341f, 0.5f));
    float r = __fmaf_rn(m, -0.693359375f, x);
    r = __fmaf_rn(m, 2.12194440e-4f, r);
    float r2 = __fmul_rn(r, r);
    float y = 1.9875691500e-4f;
    y = __fmaf_rn(y, r, 1.3981999507e-3f);
    y = __fmaf_rn(y, r, 8.3334519073e-3f);
    y = __fmaf_rn(y, r, 4.1665795894e-2f);
    y = __fmaf_rn(y, r, 1.6666665459e-1f);
    y = __fmaf_rn(y, r, 5.0000001201e-1f);
    y = __fmaf_rn(y, r2, r);
    y = __fadd_rn(y, 1.0f);
    return ldexpf(y, (int)m);
}

__device__ __forceinline__ float alpha_of(float tau) {
    return xla_expf(__fdiv_rn(-1.0f, tau));
}

// ---------------------------------------------------------------------------
// 1) maxpool 4x4 stride 4 (exact). Block 0 also resets the tile counters
//    (pool precedes all GEMM launches in stream order).
// ---------------------------------------------------------------------------
__global__ void pool_kernel(const float* __restrict__ x) {
    if (blockIdx.x == 0 && threadIdx.x == 0) { d_ctr12 = 0; d_ctr3 = 0; }
    int tid = blockIdx.x * blockDim.x + threadIdx.x;
    int i    = tid & 1023;
    int n    = (tid >> 10) & 63;
    int rest = tid >> 16;          // c*100 + t
    int t    = rest % 100;
    int c    = rest / 100;
    int ph = i >> 5, pw = i & 31;
    const float* base = x + (((size_t)(n * 100 + t) * 2 + c) << 14) + ph * 512 + pw * 4;
    float mx = -3.4e38f;
#pragma unroll
    for (int r = 0; r < 4; r++) {
        float4 v = *(const float4*)(base + r * 128);
        mx = fmaxf(mx, fmaxf(fmaxf(v.x, v.y), fmaxf(v.z, v.w)));
    }
    d_xp[tid] = mx;
}

// ---------------------------------------------------------------------------
// 2) Persistent fp32 GEMM (NT), scalar FFMA, serial ascending-k per output.
//    Tile: BM=128 x BN=64, BK=16, 256 threads, 8x4 micro-tile (round-6 math).
//    Tiles pulled via atomic counter; supports 1 or 2 source GEMMs.
// ---------------------------------------------------------------------------
#define BM 128
#define BN 64
#define BK 16
#define TILES_PER_GEMM 400   // (6400/BM) * (512/BN) = 50*8

__device__ __forceinline__ void gemm_tile(const float* __restrict__ A,
                                          const float* __restrict__ W,
                                          const float* __restrict__ bias_a,
                                          float* __restrict__ C,
                                          int rowBase, int colBase, int tid) {
    __shared__ float As[BK][BM];
    __shared__ float Ws[BK][BN];
    int tx = tid & 15;    // cols tx*4..+3
    int ty = tid >> 4;    // rows ty*8..+7
    float acc[8][4];
#pragma unroll
    for (int r = 0; r < 8; r++)
#pragma unroll
        for (int cI = 0; cI < 4; cI++) acc[r][cI] = 0.f;

    for (int k0 = 0; k0 < 1024; k0 += BK) {
        __syncthreads();
#pragma unroll
        for (int u = 0; u < 2; u++) {
            int slot = tid * 2 + u;           // 512 float4 slots
            int m = slot >> 2, kq = slot & 3;
            float4 v = *(const float4*)&A[(size_t)(rowBase + m) * 1024 + k0 + kq * 4];
            As[kq * 4 + 0][m] = v.x; As[kq * 4 + 1][m] = v.y;
            As[kq * 4 + 2][m] = v.z; As[kq * 4 + 3][m] = v.w;
        }
        {
            int nn = tid >> 2, kq = tid & 3;  // 256 float4 slots
            float4 v = *(const float4*)&W[(size_t)(colBase + nn) * 1024 + k0 + kq * 4];
            Ws[kq * 4 + 0][nn] = v.x; Ws[kq * 4 + 1][nn] = v.y;
            Ws[kq * 4 + 2][nn] = v.z; Ws[kq * 4 + 3][nn] = v.w;
        }
        __syncthreads();
        // strict ascending k, one serial fp32 chain per output
#pragma unroll
        for (int k = 0; k < BK; k++) {
            float a[8], w[4];
#pragma unroll
            for (int r = 0; r < 8; r++) a[r] = As[k][ty * 8 + r];
#pragma unroll
            for (int cI = 0; cI < 4; cI++) w[cI] = Ws[k][tx * 4 + cI];
#pragma unroll
            for (int r = 0; r < 8; r++)
#pragma unroll
                for (int cI = 0; cI < 4; cI++)
                    acc[r][cI] = __fmaf_rn(a[r], w[cI], acc[r][cI]);
        }
    }
    __syncthreads();   // compute done before caller may rewrite tile index / smem
    float badd[4];
#pragma unroll
    for (int cI = 0; cI < 4; cI++)
        badd[cI] = bias_a ? bias_a[colBase + tx * 4 + cI] : 0.f;   // zeros in practice
#pragma unroll
    for (int r = 0; r < 8; r++) {
        size_t rowOff = (size_t)(rowBase + ty * 8 + r) * 512 + colBase + tx * 4;
#pragma unroll
        for (int cI = 0; cI < 4; cI++)
            C[rowOff + cI] = __fadd_rn(acc[r][cI], badd[cI]);
    }
}

__global__ __launch_bounds__(256)
void gemm12_kernel(const float* __restrict__ w1, const float* __restrict__ b1,
                   const float* __restrict__ w2, const float* __restrict__ b2) {
    __shared__ int tileS;
    int tid = threadIdx.x;
    for (;;) {
        if (tid == 0) tileS = atomicAdd(&d_ctr12, 1);
        __syncthreads();
        int tile = tileS;
        if (tile >= 2 * TILES_PER_GEMM) return;
        int ch = tile >= TILES_PER_GEMM;
        int r  = tile - ch * TILES_PER_GEMM;
        int by = r >> 3, bx = r & 7;
        const float* A = d_xp + (size_t)ch * T_STEPS * NBATCH * INSZ;
        gemm_tile(A, ch ? w2 : w1, ch ? b2 : b1,
                  d_in12 + (size_t)ch * T_STEPS * NBATCH * HID,
                  by * BM, bx * BN, tid);
    }
}

__global__ __launch_bounds__(256)
void gemm3_kernel(const float* __restrict__ w3, const float* __restrict__ b3) {
    __shared__ int tileS;
    int tid = threadIdx.x;
    for (;;) {
        if (tid == 0) tileS = atomicAdd(&d_ctr3, 1);
        __syncthreads();
        int tile = tileS;
        if (tile >= TILES_PER_GEMM) return;
        int by = tile >> 3, bx = tile & 7;
        gemm_tile(d_s12, w3, b3, d_ff3, by * BM, bx * BN, tid);
    }
}

// ---------------------------------------------------------------------------
// ALIF update: XLA HLO op-for-op — every op individually rounded, no FMA.
// ---------------------------------------------------------------------------
__device__ __forceinline__ void alif(float inp, float& m, float& s, float& bb,
                                     float alpha, float omAlpha, float ro, float omRo) {
    bb = __fadd_rn(__fmul_rn(ro, bb), __fmul_rn(omRo, s));
    float B = __fadd_rn(0.1f, __fmul_rn(1.8f, bb));
    float t1 = __fadd_rn(__fmul_rn(m, alpha), __fmul_rn(omAlpha, inp));
    m = __fsub_rn(t1, __fmul_rn(B, s));
    s = (__fsub_rn(m, B) > 0.f) ? 1.f : 0.f;
}

// ---------------------------------------------------------------------------
// 3) Layers 1 & 2 scans — parallel per neuron, 8-deep load pipeline (MLP=8)
// ---------------------------------------------------------------------------
__global__ void scan12_kernel(const float* __restrict__ tau_adp1, const float* __restrict__ tau_adp2,
                              const float* __restrict__ tau_m1,  const float* __restrict__ tau_m2) {
    int tid = blockIdx.x * blockDim.x + threadIdx.x;   // 65536
    int h = tid & 511;
    int n = (tid >> 9) & 63;
    int layer = tid >> 15;
    float alpha = alpha_of(layer ? tau_m2[h]   : tau_m1[h]);
    float ro    = alpha_of(layer ? tau_adp2[h] : tau_adp1[h]);
    float omA = __fsub_rn(1.0f, alpha);
    float omR = __fsub_rn(1.0f, ro);
    float m = 0.f, bb = 0.1f, s = 0.f;
    const float* inbase = d_in12 + (size_t)layer * T_STEPS * NBATCH * HID + (size_t)n * HID + h;
    float* sbase = d_s12 + (size_t)n * INSZ + layer * HID + h;

    float buf[8];
#pragma unroll
    for (int j = 0; j < 8; j++) buf[j] = inbase[(size_t)j * NBATCH * HID];
    for (int t = 0; t < T_STEPS; t++) {
        float inp = buf[t & 7];
        if (t + 8 < T_STEPS) buf[t & 7] = inbase[(size_t)(t + 8) * NBATCH * HID];
        alif(inp, m, s, bb, alpha, omA, ro, omR);
        sbase[(size_t)t * NBATCH * INSZ] = s;
    }
}

// ---------------------------------------------------------------------------
// 4) transpose w_h2h3 [512][512] -> wt[j][i]  (pure copy, exact)
// ---------------------------------------------------------------------------
__global__ void transpose512(const float* __restrict__ w) {
    __shared__ float tile[32][33];
    int bx = blockIdx.x * 32, by = blockIdx.y * 32;
#pragma unroll
    for (int r = 0; r < 4; r++)
        tile[threadIdx.y + 8 * r][threadIdx.x] = w[(size_t)(by + threadIdx.y + 8 * r) * 512 + bx + threadIdx.x];
    __syncthreads();
#pragma unroll
    for (int r = 0; r < 4; r++)
        d_wt[(size_t)(bx + threadIdx.y + 8 * r) * 512 + by + threadIdx.x] =
            tile[threadIdx.x][threadIdx.y + 8 * r];
}

// ---------------------------------------------------------------------------
// 5) Layer-3 sequential scan. One CTA/batch, one thread/neuron.
//    Parity-double-buffered active list -> 2 barriers/step.
//    recur = single serial ascending-j fp32 add chain (bit-exact vs dense).
// ---------------------------------------------------------------------------
__global__ __launch_bounds__(512)
void layer3_kernel(const float* __restrict__ w_h2o3, const float* __restrict__ b_h2o3,
                   const float* __restrict__ b_h2h3,
                   const float* __restrict__ tau_adp, const float* __restrict__ tau_m,
                   float* __restrict__ out) {
    int n = blockIdx.x;      // batch
    int i = threadIdx.x;     // neuron
    __shared__ int   list[2][512];
    __shared__ int   warpcnt[2][16];
    __shared__ float s3sm[512];

    float alpha = alpha_of(tau_m[i]);
    float ro    = alpha_of(tau_adp[i]);
    float omA = __fsub_rn(1.0f, alpha);
    float omR = __fsub_rn(1.0f, ro);
    float b2  = b_h2h3[i];   // zero in practice
    float m = 0.f, bb = 0.1f, s = 0.f;
    int wid = i >> 5, lane = i & 31;
    unsigned lanemask = (1u << lane) - 1u;

    for (int t = 0; t < T_STEPS; t++) {
        int p = t & 1;
        unsigned mask = __ballot_sync(0xffffffffu, s != 0.f);
        if (lane == 0) warpcnt[p][wid] = __popc(mask);
        __syncthreads();
        int off = 0, total = 0;
#pragma unroll
        for (int w = 0; w < 16; w++) { int c = warpcnt[p][w]; total += c; if (w < wid) off += c; }
        if (s != 0.f) list[p][off + __popc(mask & lanemask)] = i;   // ascending j
        __syncthreads();

        float recur = 0.f;
#pragma unroll 4
        for (int k = 0; k < total; k++)
            recur = __fadd_rn(recur, d_wt[(size_t)list[p][k] * 512 + i]);

        float ffv = d_ff3[((size_t)t * NBATCH + n) * HID + i];   // concat@W1 + b1
        float inp = __fadd_rn(__fadd_rn(ffv, recur), b2);        // ((..)+recur)+b2
        alif(inp, m, s, bb, alpha, omA, ro, omR);
    }
    s3sm[i] = s;
    __syncthreads();
    if (i < 11) {
        float acc = 0.f;
        for (int j = 0; j < 512; j++)
            acc = __fmaf_rn(s3sm[j], w_h2o3[(size_t)i * 512 + j], acc);
        out[n * 11 + i] = __fadd_rn(acc, b_h2o3[i]);
    }
}

// ---------------------------------------------------------------------------
extern "C" void kernel_launch(void* const* d_in, const int* in_sizes, int n_in,
                              void* d_out, int out_size) {
    const float* x          = (const float*)d_in[0];
    const float* w_i2h1     = (const float*)d_in[1];
    const float* b_i2h1     = (const float*)d_in[2];
    const float* w_i2h2     = (const float*)d_in[3];
    const float* b_i2h2     = (const float*)d_in[4];
    const float* w_i2h3     = (const float*)d_in[5];
    const float* b_i2h3     = (const float*)d_in[6];
    const float* w_h2h3     = (const float*)d_in[7];
    const float* b_h2h3     = (const float*)d_in[8];
    const float* w_h2o3     = (const float*)d_in[9];
    const float* b_h2o3     = (const float*)d_in[10];
    const float* tau_adp_h1 = (const float*)d_in[11];
    const float* tau_adp_h2 = (const float*)d_in[12];
    const float* tau_adp_h3 = (const float*)d_in[13];
    const float* tau_m_h1   = (const float*)d_in[14];
    const float* tau_m_h2   = (const float*)d_in[15];
    const float* tau_m_h3   = (const float*)d_in[16];
    float* out = (float*)d_out;

    pool_kernel<<<51200, 256>>>(x);                     // also resets tile counters

    gemm12_kernel<<<296, 256>>>(w_i2h1, b_i2h1, w_i2h2, b_i2h2);

    scan12_kernel<<<256, 256>>>(tau_adp_h1, tau_adp_h2, tau_m_h1, tau_m_h2);

    transpose512<<<dim3(16, 16), dim3(32, 8)>>>(w_h2h3);

    gemm3_kernel<<<296, 256>>>(w_i2h3, b_i2h3);

    layer3_kernel<<<NBATCH, 512>>>(w_h2o3, b_h2o3, b_h2h3, tau_adp_h3, tau_m_h3, out);
}

// round 10
// speedup vs baseline: 1.6221x; 1.3527x over previous
#include <cuda_runtime.h>
#include <cuda_bf16.h>
#include <math.h>

// ---------------------------------------------------------------------------
// SRNN ALIF — bit-exact-vs-XLA-CPU fp32 (round 10).
// Round-6 GEMM math (scalar FFMA, serial ascending-k chain per output) with
// ping-pong smem + register prefetch (1 barrier/iter, hidden LDG latency).
// layer3: 128 threads x 4 neurons, LDG.128 weight gathers, ascending-j lists.
// ---------------------------------------------------------------------------

#define T_STEPS 100
#define NBATCH  64
#define HID     512
#define INSZ    1024

__device__ float d_xp  [2 * T_STEPS * NBATCH * INSZ];   // pooled [c][t][n][1024]
__device__ float d_in12[2 * T_STEPS * NBATCH * HID];    // ff proj [c][t][n][512]
__device__ float d_s12 [T_STEPS * NBATCH * INSZ];       // spikes s1||s2 [t][n][1024]
__device__ float d_ff3 [T_STEPS * NBATCH * HID];        // concat@W1 (+b1) [t][n][512]
__device__ float d_wt  [HID * HID];                     // w_h2h3 transposed [j][i]

// ---------------------------------------------------------------------------
// XLA:CPU exp — Cephes/Eigen pexp<float> with FMA, exact op order.
// ---------------------------------------------------------------------------
__device__ __forceinline__ float xla_expf(float x) {
    const float exp_hi = 88.723164f, exp_lo = -88.723164f;
    x = fminf(fmaxf(x, exp_lo), exp_hi);
    float m = floorf(__fmaf_rn(x, 1.44269504088896341f, 0.5f));
    float r = __fmaf_rn(m, -0.693359375f, x);
    r = __fmaf_rn(m, 2.12194440e-4f, r);
    float r2 = __fmul_rn(r, r);
    float y = 1.9875691500e-4f;
    y = __fmaf_rn(y, r, 1.3981999507e-3f);
    y = __fmaf_rn(y, r, 8.3334519073e-3f);
    y = __fmaf_rn(y, r, 4.1665795894e-2f);
    y = __fmaf_rn(y, r, 1.6666665459e-1f);
    y = __fmaf_rn(y, r, 5.0000001201e-1f);
    y = __fmaf_rn(y, r2, r);
    y = __fadd_rn(y, 1.0f);
    return ldexpf(y, (int)m);
}

__device__ __forceinline__ float alpha_of(float tau) {
    return xla_expf(__fdiv_rn(-1.0f, tau));
}

// ---------------------------------------------------------------------------
// 1) maxpool 4x4 stride 4 (exact) + transpose of w_h2h3 folded in as extra
//    blocks. Blocks [0,51200): pool; [51200,51456): transpose.
// ---------------------------------------------------------------------------
__global__ void pool_tr_kernel(const float* __restrict__ x,
                               const float* __restrict__ w) {
    if (blockIdx.x < 51200) {
        int tid = blockIdx.x * blockDim.x + threadIdx.x;
        int i    = tid & 1023;
        int n    = (tid >> 10) & 63;
        int rest = tid >> 16;          // c*100 + t
        int t    = rest % 100;
        int c    = rest / 100;
        int ph = i >> 5, pw = i & 31;
        const float* base = x + (((size_t)(n * 100 + t) * 2 + c) << 14) + ph * 512 + pw * 4;
        float mx = -3.4e38f;
#pragma unroll
        for (int r = 0; r < 4; r++) {
            float4 v = *(const float4*)(base + r * 128);
            mx = fmaxf(mx, fmaxf(fmaxf(v.x, v.y), fmaxf(v.z, v.w)));
        }
        d_xp[tid] = mx;
    } else {
        __shared__ float tile[32][33];
        int b  = blockIdx.x - 51200;       // 0..255
        int bx = (b & 15) * 32, by = (b >> 4) * 32;
        int tx = threadIdx.x & 31, ty = threadIdx.x >> 5;   // 32 x 8
#pragma unroll
        for (int r = 0; r < 4; r++)
            tile[ty + 8 * r][tx] = w[(size_t)(by + ty + 8 * r) * 512 + bx + tx];
        __syncthreads();
#pragma unroll
        for (int r = 0; r < 4; r++)
            d_wt[(size_t)(bx + ty + 8 * r) * 512 + by + tx] = tile[tx][ty + 8 * r];
    }
}

// ---------------------------------------------------------------------------
// 2) fp32 GEMM (NT), serial ascending-k FFMA per output (round-6 math),
//    ping-pong smem + register prefetch, 1 barrier per k-tile.
//    C[6400][512] = A[6400][1024] * W[512][1024]^T + bias
// ---------------------------------------------------------------------------
#define BM 128
#define BN 64
#define BK 16
__global__ __launch_bounds__(256)
void gemm_nt(const float* __restrict__ A, const float* __restrict__ W,
             const float* __restrict__ bias_a, float* __restrict__ C) {
    __shared__ float As[2][BK][BM];
    __shared__ float Ws[2][BK][BN];
    int tid = threadIdx.x;
    int rowBase = blockIdx.y * BM;
    int colBase = blockIdx.x * BN;
    int tx = tid & 15;    // cols tx*4..+3
    int ty = tid >> 4;    // rows ty*8..+7
    // loader mappings (identical to round 6)
    int mA0 = (tid * 2)     >> 2, kqA0 = (tid * 2)     & 3;
    int mA1 = (tid * 2 + 1) >> 2, kqA1 = (tid * 2 + 1) & 3;
    int nW  = tid >> 2,           kqW  = tid & 3;
    const float* Arow0 = A + (size_t)(rowBase + mA0) * 1024 + kqA0 * 4;
    const float* Arow1 = A + (size_t)(rowBase + mA1) * 1024 + kqA1 * 4;
    const float* Wrow  = W + (size_t)(colBase + nW)  * 1024 + kqW  * 4;

    float acc[8][4];
#pragma unroll
    for (int r = 0; r < 8; r++)
#pragma unroll
        for (int cI = 0; cI < 4; cI++) acc[r][cI] = 0.f;

    // preload tile 0 into buffer 0
    {
        float4 v0 = *(const float4*)Arow0;
        float4 v1 = *(const float4*)Arow1;
        float4 vw = *(const float4*)Wrow;
        As[0][kqA0 * 4 + 0][mA0] = v0.x; As[0][kqA0 * 4 + 1][mA0] = v0.y;
        As[0][kqA0 * 4 + 2][mA0] = v0.z; As[0][kqA0 * 4 + 3][mA0] = v0.w;
        As[0][kqA1 * 4 + 0][mA1] = v1.x; As[0][kqA1 * 4 + 1][mA1] = v1.y;
        As[0][kqA1 * 4 + 2][mA1] = v1.z; As[0][kqA1 * 4 + 3][mA1] = v1.w;
        Ws[0][kqW * 4 + 0][nW] = vw.x; Ws[0][kqW * 4 + 1][nW] = vw.y;
        Ws[0][kqW * 4 + 2][nW] = vw.z; Ws[0][kqW * 4 + 3][nW] = vw.w;
    }
    __syncthreads();

    for (int it = 0; it < 64; ++it) {
        int cur = it & 1;
        float4 v0, v1, vw;
        bool hn = it < 63;
        if (hn) {                       // prefetch next tile into registers
            int koff = (it + 1) * BK;
            v0 = *(const float4*)(Arow0 + koff);
            v1 = *(const float4*)(Arow1 + koff);
            vw = *(const float4*)(Wrow  + koff);
        }
        // strict ascending k, one serial fp32 chain per output
#pragma unroll
        for (int k = 0; k < BK; k++) {
            float a[8], w[4];
#pragma unroll
            for (int r = 0; r < 8; r++) a[r] = As[cur][k][ty * 8 + r];
#pragma unroll
            for (int cI = 0; cI < 4; cI++) w[cI] = Ws[cur][k][tx * 4 + cI];
#pragma unroll
            for (int r = 0; r < 8; r++)
#pragma unroll
                for (int cI = 0; cI < 4; cI++)
                    acc[r][cI] = __fmaf_rn(a[r], w[cI], acc[r][cI]);
        }
        if (hn) {                       // store prefetched tile into other buffer
            int nb = 1 - cur;
            As[nb][kqA0 * 4 + 0][mA0] = v0.x; As[nb][kqA0 * 4 + 1][mA0] = v0.y;
            As[nb][kqA0 * 4 + 2][mA0] = v0.z; As[nb][kqA0 * 4 + 3][mA0] = v0.w;
            As[nb][kqA1 * 4 + 0][mA1] = v1.x; As[nb][kqA1 * 4 + 1][mA1] = v1.y;
            As[nb][kqA1 * 4 + 2][mA1] = v1.z; As[nb][kqA1 * 4 + 3][mA1] = v1.w;
            Ws[nb][kqW * 4 + 0][nW] = vw.x; Ws[nb][kqW * 4 + 1][nW] = vw.y;
            Ws[nb][kqW * 4 + 2][nW] = vw.z; Ws[nb][kqW * 4 + 3][nW] = vw.w;
        }
        __syncthreads();
    }

    float badd[4];
#pragma unroll
    for (int cI = 0; cI < 4; cI++)
        badd[cI] = bias_a ? bias_a[colBase + tx * 4 + cI] : 0.f;   // zeros in practice
#pragma unroll
    for (int r = 0; r < 8; r++) {
        size_t rowOff = (size_t)(rowBase + ty * 8 + r) * 512 + colBase + tx * 4;
#pragma unroll
        for (int cI = 0; cI < 4; cI++)
            C[rowOff + cI] = __fadd_rn(acc[r][cI], badd[cI]);
    }
}

// ---------------------------------------------------------------------------
// ALIF update: XLA HLO op-for-op — every op individually rounded, no FMA.
// ---------------------------------------------------------------------------
__device__ __forceinline__ void alif(float inp, float& m, float& s, float& bb,
                                     float alpha, float omAlpha, float ro, float omRo) {
    bb = __fadd_rn(__fmul_rn(ro, bb), __fmul_rn(omRo, s));
    float B = __fadd_rn(0.1f, __fmul_rn(1.8f, bb));
    float t1 = __fadd_rn(__fmul_rn(m, alpha), __fmul_rn(omAlpha, inp));
    m = __fsub_rn(t1, __fmul_rn(B, s));
    s = (__fsub_rn(m, B) > 0.f) ? 1.f : 0.f;
}

// ---------------------------------------------------------------------------
// 3) Layers 1 & 2 scans — parallel per neuron, 8-deep load pipeline (MLP=8)
// ---------------------------------------------------------------------------
__global__ void scan12_kernel(const float* __restrict__ tau_adp1, const float* __restrict__ tau_adp2,
                              const float* __restrict__ tau_m1,  const float* __restrict__ tau_m2) {
    int tid = blockIdx.x * blockDim.x + threadIdx.x;   // 65536
    int h = tid & 511;
    int n = (tid >> 9) & 63;
    int layer = tid >> 15;
    float alpha = alpha_of(layer ? tau_m2[h]   : tau_m1[h]);
    float ro    = alpha_of(layer ? tau_adp2[h] : tau_adp1[h]);
    float omA = __fsub_rn(1.0f, alpha);
    float omR = __fsub_rn(1.0f, ro);
    float m = 0.f, bb = 0.1f, s = 0.f;
    const float* inbase = d_in12 + (size_t)layer * T_STEPS * NBATCH * HID + (size_t)n * HID + h;
    float* sbase = d_s12 + (size_t)n * INSZ + layer * HID + h;

    float buf[8];
#pragma unroll
    for (int j = 0; j < 8; j++) buf[j] = inbase[(size_t)j * NBATCH * HID];
    for (int t = 0; t < T_STEPS; t++) {
        float inp = buf[t & 7];
        if (t + 8 < T_STEPS) buf[t & 7] = inbase[(size_t)(t + 8) * NBATCH * HID];
        alif(inp, m, s, bb, alpha, omA, ro, omR);
        sbase[(size_t)t * NBATCH * INSZ] = s;
    }
}

// ---------------------------------------------------------------------------
// 4) Layer-3 sequential scan. One CTA/batch, 128 threads x 4 neurons.
//    Active list built in strict ascending-j order (order = (tid,k));
//    per-neuron recur = single serial ascending-j fp32 add chain (== dense).
//    Weight gathers are LDG.128 (4 neurons per thread).
// ---------------------------------------------------------------------------
__global__ __launch_bounds__(128)
void layer3_kernel(const float* __restrict__ w_h2o3, const float* __restrict__ b_h2o3,
                   const float* __restrict__ b_h2h3,
                   const float* __restrict__ tau_adp, const float* __restrict__ tau_m,
                   float* __restrict__ out) {
    int n = blockIdx.x;
    int tid = threadIdx.x;          // neurons 4*tid .. 4*tid+3
    int lane = tid & 31, wrp = tid >> 5;
    unsigned ltmask = (1u << lane) - 1u;
    __shared__ int   list[2][512];
    __shared__ int   wcnt[2][4];
    __shared__ float s3sm[512];

    float m[4], bb[4], s[4], alf[4], ro[4], omA[4], omR[4], b2[4];
#pragma unroll
    for (int k = 0; k < 4; k++) {
        int j = tid * 4 + k;
        alf[k] = alpha_of(tau_m[j]);
        ro[k]  = alpha_of(tau_adp[j]);
        omA[k] = __fsub_rn(1.0f, alf[k]);
        omR[k] = __fsub_rn(1.0f, ro[k]);
        b2[k]  = b_h2h3[j];          // zero in practice
        m[k] = 0.f; bb[k] = 0.1f; s[k] = 0.f;
    }
    const float4* wt4 = (const float4*)d_wt;   // [j][i/4] float4

    for (int t = 0; t < T_STEPS; t++) {
        int p = t & 1;
        unsigned bal[4];
#pragma unroll
        for (int k = 0; k < 4; k++)
            bal[k] = __ballot_sync(0xffffffffu, s[k] != 0.f);
        int offw = 0, cntw = 0;
#pragma unroll
        for (int k = 0; k < 4; k++) {
            offw += __popc(bal[k] & ltmask);   // actives of earlier lanes (all k)
            cntw += __popc(bal[k]);
        }
        if (lane == 0) wcnt[p][wrp] = cntw;
        __syncthreads();
        int base = 0, total = 0;
#pragma unroll
        for (int w = 0; w < 4; w++) { int c = wcnt[p][w]; total += c; if (w < wrp) base += c; }
        int pos = base + offw;
#pragma unroll
        for (int k = 0; k < 4; k++)            // own actives, k ascending -> j ascending
            if (s[k] != 0.f) list[p][pos++] = tid * 4 + k;
        __syncthreads();

        // 4 per-neuron serial chains over ascending-j actives (bit-exact vs dense)
        float rec[4] = {0.f, 0.f, 0.f, 0.f};
#pragma unroll 4
        for (int e = 0; e < total; e++) {
            float4 wv = wt4[(size_t)list[p][e] * 128 + tid];
            rec[0] = __fadd_rn(rec[0], wv.x);
            rec[1] = __fadd_rn(rec[1], wv.y);
            rec[2] = __fadd_rn(rec[2], wv.z);
            rec[3] = __fadd_rn(rec[3], wv.w);
        }

        float4 ffv = *(const float4*)&d_ff3[((size_t)t * NBATCH + n) * HID + tid * 4];
        float ff[4] = {ffv.x, ffv.y, ffv.z, ffv.w};
#pragma unroll
        for (int k = 0; k < 4; k++) {
            float inp = __fadd_rn(__fadd_rn(ff[k], rec[k]), b2[k]);
            alif(inp, m[k], s[k], bb[k], alf[k], omA[k], ro[k], omR[k]);
        }
    }
#pragma unroll
    for (int k = 0; k < 4; k++) s3sm[tid * 4 + k] = s[k];
    __syncthreads();
    if (tid < 11) {
        float acc = 0.f;
        for (int j = 0; j < 512; j++)
            acc = __fmaf_rn(s3sm[j], w_h2o3[(size_t)tid * 512 + j], acc);
        out[n * 11 + tid] = __fadd_rn(acc, b_h2o3[tid]);
    }
}

// ---------------------------------------------------------------------------
extern "C" void kernel_launch(void* const* d_in, const int* in_sizes, int n_in,
                              void* d_out, int out_size) {
    const float* x          = (const float*)d_in[0];
    const float* w_i2h1     = (const float*)d_in[1];
    const float* b_i2h1     = (const float*)d_in[2];
    const float* w_i2h2     = (const float*)d_in[3];
    const float* b_i2h2     = (const float*)d_in[4];
    const float* w_i2h3     = (const float*)d_in[5];
    const float* b_i2h3     = (const float*)d_in[6];
    const float* w_h2h3     = (const float*)d_in[7];
    const float* b_h2h3     = (const float*)d_in[8];
    const float* w_h2o3     = (const float*)d_in[9];
    const float* b_h2o3     = (const float*)d_in[10];
    const float* tau_adp_h1 = (const float*)d_in[11];
    const float* tau_adp_h2 = (const float*)d_in[12];
    const float* tau_adp_h3 = (const float*)d_in[13];
    const float* tau_m_h1   = (const float*)d_in[14];
    const float* tau_m_h2   = (const float*)d_in[15];
    const float* tau_m_h3   = (const float*)d_in[16];
    float* out = (float*)d_out;

    float *xp, *in12, *s12, *ff3;
    cudaGetSymbolAddress((void**)&xp,   d_xp);
    cudaGetSymbolAddress((void**)&in12, d_in12);
    cudaGetSymbolAddress((void**)&s12,  d_s12);
    cudaGetSymbolAddress((void**)&ff3,  d_ff3);

    pool_tr_kernel<<<51456, 256>>>(x, w_h2h3);   // pool + weight transpose

    dim3 ggrid(512 / BN, 6400 / BM);
    gemm_nt<<<ggrid, 256>>>(xp,                                   w_i2h1, b_i2h1, in12);
    gemm_nt<<<ggrid, 256>>>(xp + (size_t)T_STEPS * NBATCH * INSZ, w_i2h2, b_i2h2,
                            in12 + (size_t)T_STEPS * NBATCH * HID);

    scan12_kernel<<<256, 256>>>(tau_adp_h1, tau_adp_h2, tau_m_h1, tau_m_h2);

    gemm_nt<<<ggrid, 256>>>(s12, w_i2h3, b_i2h3, ff3);

    layer3_kernel<<<NBATCH, 128>>>(w_h2o3, b_h2o3, b_h2h3, tau_adp_h3, tau_m_h3, out);
}